// round 1
// baseline (speedup 1.0000x reference)
#include <cuda_runtime.h>

// Problem constants (from reference):
//   features: [B=4, C=256, H=64, W=64] fp32
//   rois:     [R=2048, 5] (batch, x1, y1, x2, y2), SPATIAL_SCALE = 0.25
//   RoDAlign grid AH=AW=10, sample positions h=w={0,7,...,63} -> EXACT gather
//   output:   [R, C, 9, 9] fp32  (maxpool 2x2 stride 1 of masked 10x10 grid)

#define BATCH 4
#define NCH   256
#define NPOS  100      // 10x10 grid
#define CHB   64       // channels per block in main kernel
#define NCHUNK (NCH / CHB)

// Precomputed gather G[b][c][i*10+j] = features[b,c,7i,7j]
__device__ float g_G[BATCH * NCH * NPOS];

__global__ void gather_grid_kernel(const float* __restrict__ feat) {
    int idx = blockIdx.x * blockDim.x + threadIdx.x;
    if (idx >= BATCH * NCH * NPOS) return;
    int pos = idx % NPOS;          // i*10 + j
    int bc  = idx / NPOS;          // b*256 + c
    int i = pos / 10;
    int j = pos % 10;
    // features[bc][7i][7j], plane is 64x64
    g_G[idx] = feat[(bc * 64 + i * 7) * 64 + j * 7];
}

__global__ __launch_bounds__(256) void rod_align_max_kernel(
    const float* __restrict__ rois,
    float* __restrict__ out)
{
    __shared__ float s[CHB * NPOS];   // masked grid values for this channel chunk
    __shared__ float smask[NPOS];     // 0.0 if inside ROI (discard), 1.0 otherwise

    const int r     = blockIdx.x;     // roi index
    const int chunk = blockIdx.y;     // channel chunk
    const int tid   = threadIdx.x;

    // ROI parameters (broadcast loads, L2/L1 hit after first block touches them)
    const float x1 = rois[r * 5 + 1] * 0.25f;
    const float y1 = rois[r * 5 + 2] * 0.25f;
    const float x2 = rois[r * 5 + 3] * 0.25f;
    const float y2 = rois[r * 5 + 4] * 0.25f;
    const int   b  = (int)rois[r * 5 + 0];

    if (tid < NPOS) {
        float h = (float)(tid / 10) * 7.0f;
        float w = (float)(tid % 10) * 7.0f;
        bool inside = (h >= y1) & (h <= y2) & (w >= x1) & (w <= x2);
        smask[tid] = inside ? 0.0f : 1.0f;
    }
    __syncthreads();

    // Load this chunk's grid values, pre-multiplied by the region-of-discard mask.
    const float* gsrc = g_G + (b * NCH + chunk * CHB) * NPOS;
    #pragma unroll
    for (int k = tid; k < CHB * NPOS; k += 256) {
        s[k] = gsrc[k] * smask[k % NPOS];
    }
    __syncthreads();

    // 2x2 stride-1 maxpool over the masked 10x10 grid -> 9x9 per channel.
    float* o = out + (size_t)(r * NCH + chunk * CHB) * 81;
    for (int k = tid; k < CHB * 81; k += 256) {
        int c   = k / 81;
        int rem = k % 81;
        int i   = rem / 9;
        int j   = rem - i * 9;
        int p   = c * NPOS + i * 10 + j;
        float v0 = fmaxf(s[p],      s[p + 1]);
        float v1 = fmaxf(s[p + 10], s[p + 11]);
        o[k] = fmaxf(v0, v1);
    }
}

extern "C" void kernel_launch(void* const* d_in, const int* in_sizes, int n_in,
                              void* d_out, int out_size) {
    const float* features = (const float*)d_in[0];   // [4,256,64,64]
    const float* rois     = (const float*)d_in[1];   // [2048,5]
    float* out = (float*)d_out;                      // [2048,256,9,9]

    const int R = in_sizes[1] / 5;                   // 2048

    // 1) Gather the ROI-independent sample grid (exact: positions are integer).
    int n_g = BATCH * NCH * NPOS;
    gather_grid_kernel<<<(n_g + 255) / 256, 256>>>(features);

    // 2) Per-ROI mask + maxpool, write final output.
    dim3 grid(R, NCHUNK);
    rod_align_max_kernel<<<grid, 256>>>(rois, out);
}

// round 2
// speedup vs baseline: 1.3675x; 1.3675x over previous
#include <cuda_runtime.h>

// Problem constants:
//   features: [B=4, C=256, H=64, W=64] fp32
//   rois:     [R=2048, 5] (batch, x1, y1, x2, y2), SPATIAL_SCALE = 0.25
//   Grid positions h=w={0,7,...,63} are EXACT integers -> bilinear == gather.
//   output:   [R, C, 9, 9] fp32  (maxpool 2x2 s1 of region-of-discard-masked 10x10)

#define BATCH 4
#define NCH   256
#define NPOS  100        // 10x10 grid per channel
#define CHB   64         // channels per block
#define NCHUNK (NCH / CHB)
#define THREADS 288      // 9 warps; 64 ch * 9 rows = 576 strips = 2 per thread

// Precomputed gather G[b][c][i*10+j] = features[b,c,7i,7j]  (400 KB, L2-resident)
__device__ float g_G[BATCH * NCH * NPOS];

__global__ void gather_grid_kernel(const float* __restrict__ feat) {
    int idx = blockIdx.x * blockDim.x + threadIdx.x;
    if (idx >= BATCH * NCH * NPOS) return;
    int pos = idx % NPOS;
    int bc  = idx / NPOS;
    int i = pos / 10;
    int j = pos % 10;
    g_G[idx] = feat[(bc * 64 + i * 7) * 64 + j * 7];
}

__global__ __launch_bounds__(THREADS) void rod_align_max_kernel(
    const float* __restrict__ rois,
    float* __restrict__ out)
{
    __shared__ float sout[CHB * 81];   // 20736 B staged outputs

    const int r     = blockIdx.x;
    const int chunk = blockIdx.y;
    const int tid   = threadIdx.x;

    const float x1 = rois[r * 5 + 1] * 0.25f;
    const float y1 = rois[r * 5 + 2] * 0.25f;
    const float x2 = rois[r * 5 + 3] * 0.25f;
    const float y2 = rois[r * 5 + 4] * 0.25f;
    const int   b  = (int)rois[r * 5 + 0];

    // Column inside-mask (same for both strips of this thread).
    bool inw[10];
    #pragma unroll
    for (int j = 0; j < 10; j++) {
        float w = (float)j * 7.0f;
        inw[j] = (w >= x1) && (w <= x2);
    }

    const float* Gbase = g_G + (b * NCH + chunk * CHB) * NPOS;

    #pragma unroll
    for (int it = 0; it < 2; it++) {
        int s = tid + it * THREADS;      // strip id in [0, 576)
        int c = s / 9;                   // channel within chunk
        int i = s - c * 9;               // output row

        // Two grid rows for this strip, via aligned 8B loads
        // (offset c*100 + i*10 is even -> float2-aligned).
        const float2* g2 = (const float2*)(Gbase + c * NPOS + i * 10);
        float r0[10], r1[10];
        #pragma unroll
        for (int q = 0; q < 5; q++) {
            float2 t0 = g2[q];
            float2 t1 = g2[q + 5];
            r0[2 * q] = t0.x;  r0[2 * q + 1] = t0.y;
            r1[2 * q] = t1.x;  r1[2 * q + 1] = t1.y;
        }

        float h0 = (float)i * 7.0f;
        float h1 = h0 + 7.0f;
        bool inh0 = (h0 >= y1) && (h0 <= y2);
        bool inh1 = (h1 >= y1) && (h1 <= y2);

        // Masked vertical max into rm[0..9]
        float rm[10];
        #pragma unroll
        for (int j = 0; j < 10; j++) {
            float a = (inh0 && inw[j]) ? 0.0f : r0[j];
            float d = (inh1 && inw[j]) ? 0.0f : r1[j];
            rm[j] = fmaxf(a, d);
        }

        // Horizontal max -> 9 outputs; base 9*s, stride 9 across threads
        // (9 coprime 32 -> conflict-free STS).
        float* so = sout + s * 9;
        #pragma unroll
        for (int j = 0; j < 9; j++)
            so[j] = fmaxf(rm[j], rm[j + 1]);
    }
    __syncthreads();

    // Coalesced vectorized writeout: 5184 floats = 1296 float4.
    // Block output base = (r*256 + chunk*64)*81*4 B = n*20736 B -> 16B aligned.
    float4* o4 = (float4*)(out + (size_t)(r * NCH + chunk * CHB) * 81);
    const float4* s4 = (const float4*)sout;
    #pragma unroll
    for (int k = tid; k < (CHB * 81) / 4; k += THREADS)
        o4[k] = s4[k];
}

extern "C" void kernel_launch(void* const* d_in, const int* in_sizes, int n_in,
                              void* d_out, int out_size) {
    const float* features = (const float*)d_in[0];   // [4,256,64,64]
    const float* rois     = (const float*)d_in[1];   // [2048,5]
    float* out = (float*)d_out;                      // [2048,256,9,9]

    const int R = in_sizes[1] / 5;                   // 2048

    int n_g = BATCH * NCH * NPOS;
    gather_grid_kernel<<<(n_g + 255) / 256, 256>>>(features);

    dim3 grid(R, NCHUNK);
    rod_align_max_kernel<<<grid, THREADS>>>(rois, out);
}